// round 6
// baseline (speedup 1.0000x reference)
#include <cuda_runtime.h>
#include <cuda_fp16.h>
#include <math.h>

#define NN 50000
#define NE 800000
#define D 128
#define NB 196   // (NN + 255) / 256

// ---------------- device scratch (no allocations allowed) ----------------
__device__ int    g_deg_in[NN];
__device__ int    g_deg_out[NN];
__device__ int    g_row_ptr[NN + 1];
__device__ int    g_cursor[NN];
__device__ int    g_col[NE];
__device__ int    g_bsum[NB];
__device__ int    g_dbin[64];
__device__ int    g_dcur[64];
__device__ int    g_perm[NN];
__device__ float  g_invd1[NN];
__device__ float  g_innorm[NN];
__device__ float  g_outnorm[NN];
__device__ __half g_t [NN * D];
__device__ __half g_y1[NN * D];
__device__ __half g_y2[NN * D];
__device__ float  g_Wt[D * D];
__device__ float  g_Wc[D * D];
__device__ float  g_bt[D];
__device__ float  g_bw[D];

__device__ __forceinline__ uint2 f4_to_h4(float x, float y, float z, float w) {
    __half2 a = __floats2half2_rn(x, y);
    __half2 b = __floats2half2_rn(z, w);
    uint2 u;
    u.x = *(unsigned*)&a;
    u.y = *(unsigned*)&b;
    return u;
}

__device__ __forceinline__ void add_h8(float* a, uint4 v) {
    __half2* h = (__half2*)&v;
    #pragma unroll
    for (int i = 0; i < 4; i++) {
        float2 f = __half22float2(h[i]);
        a[2 * i]     += f.x;
        a[2 * i + 1] += f.y;
    }
}

// ---------------- graph preprocessing (worker stream) ----------------
__global__ void k_hist(const int* __restrict__ src, const int* __restrict__ dst) {
    int i = blockIdx.x * blockDim.x + threadIdx.x;
    if (i < NE / 2) {
        int2 s = __ldg(&((const int2*)src)[i]);
        int2 d = __ldg(&((const int2*)dst)[i]);
        atomicAdd(&g_deg_in[d.x], 1);
        atomicAdd(&g_deg_in[d.y], 1);
        atomicAdd(&g_deg_out[s.x], 1);
        atomicAdd(&g_deg_out[s.y], 1);
    }
}

__global__ void k_partial() {
    __shared__ int ws[8];
    int tid = threadIdx.x, lane = tid & 31, wid = tid >> 5;
    int i = blockIdx.x * 256 + tid;
    int v = (i < NN) ? g_deg_in[i] : 0;
    #pragma unroll
    for (int off = 16; off > 0; off >>= 1) v += __shfl_down_sync(0xffffffffu, v, off);
    if (lane == 0) ws[wid] = v;
    __syncthreads();
    if (tid == 0) {
        int s = 0;
        #pragma unroll
        for (int j = 0; j < 8; j++) s += ws[j];
        g_bsum[blockIdx.x] = s;
    }
}

// fused: block base = sum of g_bsum[0..bid) computed in-kernel; then intra-block scan
__global__ void k_rowptr() {
    __shared__ int ws[8];
    __shared__ int s_base;
    int tid = threadIdx.x, lane = tid & 31, wid = tid >> 5;

    int v0 = (tid < blockIdx.x) ? g_bsum[tid] : 0;
    #pragma unroll
    for (int off = 16; off > 0; off >>= 1) v0 += __shfl_down_sync(0xffffffffu, v0, off);
    if (lane == 0) ws[wid] = v0;
    __syncthreads();
    if (tid == 0) {
        int s = 0;
        #pragma unroll
        for (int j = 0; j < 8; j++) s += ws[j];
        s_base = s;
    }
    __syncthreads();

    int i = blockIdx.x * 256 + tid;
    int v = (i < NN) ? g_deg_in[i] : 0;
    int incl = v;
    #pragma unroll
    for (int off = 1; off < 32; off <<= 1) {
        int t = __shfl_up_sync(0xffffffffu, incl, off);
        if (lane >= off) incl += t;
    }
    if (lane == 31) ws[wid] = incl;
    __syncthreads();
    if (wid == 0 && lane < 8) {
        int s = ws[lane];
        #pragma unroll
        for (int off = 1; off < 8; off <<= 1) {
            int t = __shfl_up_sync(0xffu, s, off);
            if (lane >= off) s += t;
        }
        ws[lane] = s;
    }
    __syncthreads();
    int base = s_base + (wid > 0 ? ws[wid - 1] : 0);
    if (i < NN) {
        int excl = base + incl - v;
        g_row_ptr[i + 1] = base + incl;
        g_cursor[i] = excl;
        int di = v, dq = g_deg_out[i];
        g_invd1[i]   = 1.0f / (float)(di + 1);
        g_innorm[i]  = rsqrtf((float)(di > 0 ? di : 1));
        g_outnorm[i] = rsqrtf((float)(dq > 0 ? dq : 1));
    }
    if (i == 0) g_row_ptr[0] = 0;
}

__global__ void k_scatter(const int* __restrict__ src, const int* __restrict__ dst) {
    int i = blockIdx.x * blockDim.x + threadIdx.x;
    if (i < NE / 2) {
        int2 s = __ldg(&((const int2*)src)[i]);
        int2 d = __ldg(&((const int2*)dst)[i]);
        int p0 = atomicAdd(&g_cursor[d.x], 1);
        g_col[p0] = s.x;
        int p1 = atomicAdd(&g_cursor[d.y], 1);
        g_col[p1] = s.y;
    }
}

// ---------------- degree-balanced permutation (counting sort by in-degree) ----------------
__global__ void k_dhist() {
    int i = blockIdx.x * blockDim.x + threadIdx.x;
    if (i < NN) {
        int b = g_deg_in[i]; if (b > 63) b = 63;
        atomicAdd(&g_dbin[b], 1);
    }
}
__global__ void k_dscan() {
    // single thread: 64 bins, trivial
    int run = 0;
    for (int b = 0; b < 64; b++) { g_dcur[b] = run; run += g_dbin[b]; }
}
__global__ void k_dperm() {
    int i = blockIdx.x * blockDim.x + threadIdx.x;
    if (i < NN) {
        int b = g_deg_in[i]; if (b > 63) b = 63;
        int p = atomicAdd(&g_dcur[b], 1);
        g_perm[p] = i;
    }
}

// ---------------- fused weight precompute ----------------
__global__ void k_wA(const float* __restrict__ W1, const float* __restrict__ b1,
                     const float* __restrict__ W2, const float* __restrict__ b2) {
    int r = blockIdx.x, c = threadIdx.x;
    __shared__ float arow[D];
    arow[c] = (r < D) ? W1[r * D + c] : b1[c];
    __syncthreads();
    float a0 = 0.f, a1 = 0.f, a2 = 0.f, a3 = 0.f;
    #pragma unroll 8
    for (int k = 0; k < D; k += 4) {
        a0 += arow[k + 0] * __ldg(&W2[(k + 0) * D + c]);
        a1 += arow[k + 1] * __ldg(&W2[(k + 1) * D + c]);
        a2 += arow[k + 2] * __ldg(&W2[(k + 2) * D + c]);
        a3 += arow[k + 3] * __ldg(&W2[(k + 3) * D + c]);
    }
    float acc = (a0 + a1) + (a2 + a3);
    if (r < D) g_Wt[r * D + c] = acc;
    else       g_bt[c] = acc + b2[c];
}
__global__ void k_wB(const float* __restrict__ W3) {
    int r = blockIdx.x, c = threadIdx.x;
    __shared__ float arow[D];
    arow[c] = (r < D) ? g_Wt[r * D + c] : g_bt[c];
    __syncthreads();
    float a0 = 0.f, a1 = 0.f, a2 = 0.f, a3 = 0.f;
    #pragma unroll 8
    for (int k = 0; k < D; k += 4) {
        a0 += arow[k + 0] * __ldg(&W3[(k + 0) * D + c]);
        a1 += arow[k + 1] * __ldg(&W3[(k + 1) * D + c]);
        a2 += arow[k + 2] * __ldg(&W3[(k + 2) * D + c]);
        a3 += arow[k + 3] * __ldg(&W3[(k + 3) * D + c]);
    }
    float acc = (a0 + a1) + (a2 + a3);
    if (r < D) g_Wc[r * D + c] = acc;
    else       g_bw[c] = acc;
}

// ---------------- front GEMM: g_t = x @ Wc  (fp32 in, fp16 out) ----------------
__global__ void k_gemm(const float* __restrict__ x) {
    int t = blockIdx.x * blockDim.x + threadIdx.x;
    int w = t >> 5;
    int lane = t & 31;
    int r0 = w * 4;
    if (r0 >= NN) return;

    const float4* Wc4 = (const float4*)g_Wc;
    const float4* x4  = (const float4*)x;

    float4 acc0 = make_float4(0.f, 0.f, 0.f, 0.f);
    float4 acc1 = acc0, acc2 = acc0, acc3 = acc0;

    #pragma unroll 4
    for (int k = 0; k < D; k += 4) {
        float4 z0 = __ldg(&x4[(size_t)(r0 + 0) * 32 + (k >> 2)]);
        float4 z1 = __ldg(&x4[(size_t)(r0 + 1) * 32 + (k >> 2)]);
        float4 z2 = __ldg(&x4[(size_t)(r0 + 2) * 32 + (k >> 2)]);
        float4 z3 = __ldg(&x4[(size_t)(r0 + 3) * 32 + (k >> 2)]);
        const float* p0 = (const float*)&z0;
        const float* p1 = (const float*)&z1;
        const float* p2 = (const float*)&z2;
        const float* p3 = (const float*)&z3;
        #pragma unroll
        for (int kk = 0; kk < 4; kk++) {
            float4 wv = __ldg(&Wc4[(size_t)(k + kk) * 32 + lane]);
            float a0 = p0[kk], a1 = p1[kk], a2 = p2[kk], a3 = p3[kk];
            acc0.x += a0 * wv.x; acc0.y += a0 * wv.y; acc0.z += a0 * wv.z; acc0.w += a0 * wv.w;
            acc1.x += a1 * wv.x; acc1.y += a1 * wv.y; acc1.z += a1 * wv.z; acc1.w += a1 * wv.w;
            acc2.x += a2 * wv.x; acc2.y += a2 * wv.y; acc2.z += a2 * wv.z; acc2.w += a2 * wv.w;
            acc3.x += a3 * wv.x; acc3.y += a3 * wv.y; acc3.z += a3 * wv.z; acc3.w += a3 * wv.w;
        }
    }

    uint2* t4 = (uint2*)g_t;
    t4[(size_t)(r0 + 0) * 32 + lane] = f4_to_h4(acc0.x, acc0.y, acc0.z, acc0.w);
    t4[(size_t)(r0 + 1) * 32 + lane] = f4_to_h4(acc1.x, acc1.y, acc1.z, acc1.w);
    t4[(size_t)(r0 + 2) * 32 + lane] = f4_to_h4(acc2.x, acc2.y, acc2.z, acc2.w);
    t4[(size_t)(r0 + 3) * 32 + lane] = f4_to_h4(acc3.x, acc3.y, acc3.z, acc3.w);
}

// ---------------- aggregation (warp per node, degree-sorted, paired-edge halves) ----------
// MODE 0: y1 = (sum_neigh + self) * invd1
// MODE 1: y2 = (sum_neigh + self) * invd1 * outnorm
// MODE 2: out = innorm*sum_neigh + (innorm*sum outnorm[src])*bw + b3  (fp32 out)
template <int MODE>
__global__ __launch_bounds__(256) void k_agg(const __half* __restrict__ hin,
                                             __half* __restrict__ hout,
                                             const float* __restrict__ b3,
                                             float* __restrict__ out) {
    int t = blockIdx.x * 256 + threadIdx.x;
    int w = t >> 5;
    if (w >= NN) return;
    int node = __ldg(&g_perm[w]);         // degree-sorted assignment
    int lane = threadIdx.x & 31;
    int sl   = lane & 15;                 // feature chunk (16B of the 256B row)
    int half = lane >> 4;                 // 0: even edges, 1: odd edges

    const uint4* in8 = (const uint4*)hin;

    float acc[8] = {0.f, 0.f, 0.f, 0.f, 0.f, 0.f, 0.f, 0.f};
    float vs = 0.f;
    if (MODE < 2 && half == 0)
        add_h8(acc, __ldg(&in8[(size_t)node * 16 + sl]));   // self-term added once

    int e   = g_row_ptr[node];
    int end = g_row_ptr[node + 1];

    while (e < end) {                     // uniform bounds across warp: no divergence
        int cols[8];
        #pragma unroll
        for (int j = 0; j < 8; j++)
            cols[j] = (e + j < end) ? __ldg(&g_col[e + j]) : -1;
        #pragma unroll
        for (int j = 0; j < 4; j++) {
            int c = cols[2 * j + half];   // 2 edges per warp instruction
            if (c >= 0) {
                add_h8(acc, __ldg(&in8[(size_t)c * 16 + sl]));
                if (MODE == 2) vs += g_outnorm[c];
            }
        }
        e += 8;
    }

    // combine halves (warp fully converged here)
    #pragma unroll
    for (int i = 0; i < 8; i++)
        acc[i] += __shfl_xor_sync(0xffffffffu, acc[i], 16);
    if (MODE == 2) vs += __shfl_xor_sync(0xffffffffu, vs, 16);

    if (lane < 16) {
        if (MODE < 2) {
            float sc = (MODE == 0) ? g_invd1[node] : g_invd1[node] * g_outnorm[node];
            uint4 u;
            __half2* h = (__half2*)&u;
            #pragma unroll
            for (int i = 0; i < 4; i++)
                h[i] = __floats2half2_rn(acc[2 * i] * sc, acc[2 * i + 1] * sc);
            ((uint4*)hout)[(size_t)node * 16 + sl] = u;
        } else {
            float sc = g_innorm[node];
            float vb = vs * sc;
            const float4* bw4 = (const float4*)g_bw;
            const float4* b34 = (const float4*)b3;
            float4 bwa = __ldg(&bw4[sl * 2]),     b3a = __ldg(&b34[sl * 2]);
            float4 bwb = __ldg(&bw4[sl * 2 + 1]), b3b = __ldg(&b34[sl * 2 + 1]);
            float4 o;
            float4* o4 = (float4*)out;
            o.x = acc[0] * sc + vb * bwa.x + b3a.x;
            o.y = acc[1] * sc + vb * bwa.y + b3a.y;
            o.z = acc[2] * sc + vb * bwa.z + b3a.z;
            o.w = acc[3] * sc + vb * bwa.w + b3a.w;
            o4[(size_t)node * 32 + sl * 2] = o;
            o.x = acc[4] * sc + vb * bwb.x + b3b.x;
            o.y = acc[5] * sc + vb * bwb.y + b3b.y;
            o.z = acc[6] * sc + vb * bwb.z + b3b.z;
            o.w = acc[7] * sc + vb * bwb.w + b3b.w;
            o4[(size_t)node * 32 + sl * 2 + 1] = o;
        }
    }
}

// ---------------- launch ----------------
extern "C" void kernel_launch(void* const* d_in, const int* in_sizes, int n_in,
                              void* d_out, int out_size) {
    const float* x  = (const float*)d_in[0];
    const float* W1 = (const float*)d_in[1];
    const float* b1 = (const float*)d_in[2];
    const float* W2 = (const float*)d_in[3];
    const float* b2 = (const float*)d_in[4];
    const float* W3 = (const float*)d_in[5];
    const float* b3 = (const float*)d_in[6];
    const int* src  = (const int*)d_in[7];
    const int* dst  = (const int*)d_in[8];
    float* out = (float*)d_out;

    __half *tptr, *y1, *y2;
    void *din, *dout_deg, *dbin;
    cudaGetSymbolAddress((void**)&tptr, g_t);
    cudaGetSymbolAddress((void**)&y1, g_y1);
    cudaGetSymbolAddress((void**)&y2, g_y2);
    cudaGetSymbolAddress(&din, g_deg_in);
    cudaGetSymbolAddress(&dout_deg, g_deg_out);
    cudaGetSymbolAddress(&dbin, g_dbin);

    static cudaStream_t s1 = 0;
    static cudaEvent_t evA = 0, evB = 0;
    if (!s1) {
        cudaStreamCreateWithFlags(&s1, cudaStreamNonBlocking);
        cudaEventCreateWithFlags(&evA, cudaEventDisableTiming);
        cudaEventCreateWithFlags(&evB, cudaEventDisableTiming);
    }

    // ---- fork: CSR build + degree sort on worker stream s1 ----
    cudaEventRecord(evA, 0);
    cudaStreamWaitEvent(s1, evA, 0);
    cudaMemsetAsync(din, 0, NN * sizeof(int), s1);
    cudaMemsetAsync(dout_deg, 0, NN * sizeof(int), s1);
    cudaMemsetAsync(dbin, 0, 64 * sizeof(int), s1);
    k_hist   <<<(NE / 2 + 255) / 256, 256, 0, s1>>>(src, dst);
    k_partial<<<NB, 256, 0, s1>>>();
    k_rowptr <<<NB, 256, 0, s1>>>();
    k_scatter<<<(NE / 2 + 255) / 256, 256, 0, s1>>>(src, dst);
    k_dhist  <<<NB, 256, 0, s1>>>();
    k_dscan  <<<1, 1, 0, s1>>>();
    k_dperm  <<<NB, 256, 0, s1>>>();
    cudaEventRecord(evB, s1);

    // ---- main stream: weights -> front GEMM ----
    k_wA<<<D + 1, D>>>(W1, b1, W2, b2);
    k_wB<<<D + 1, D>>>(W3);

    const int FIN_WARPS = (NN + 3) / 4;
    const int FIN_BLOCKS = (FIN_WARPS * 32 + 255) / 256;
    k_gemm<<<FIN_BLOCKS, 256>>>(x);

    // ---- join: agg passes need both GEMM output and CSR ----
    cudaStreamWaitEvent(0, evB, 0);

    const int AGG_BLOCKS = (NN * 32 + 255) / 256;   // 6250 (warp per node)
    k_agg<0><<<AGG_BLOCKS, 256>>>(tptr, y1, nullptr, nullptr);
    k_agg<1><<<AGG_BLOCKS, 256>>>(y1, y2, nullptr, nullptr);
    k_agg<2><<<AGG_BLOCKS, 256>>>(y2, nullptr, b3, out);
}

// round 7
// speedup vs baseline: 1.1711x; 1.1711x over previous
#include <cuda_runtime.h>
#include <cuda_fp16.h>
#include <math.h>

#define NN 50000
#define NE 800000
#define D 128
#define NB 196   // (NN + 255) / 256

// ---------------- device scratch (no allocations allowed) ----------------
__device__ int    g_deg_in[NN];
__device__ int    g_deg_out[NN];
__device__ int    g_row_ptr[NN + 1];
__device__ int    g_cursor[NN];
__device__ int    g_col[NE];
__device__ int    g_bsum[NB];
__device__ float  g_invd1[NN];
__device__ float  g_innorm[NN];
__device__ float  g_outnorm[NN];
__device__ float  g_v[NN];
__device__ __half g_t [NN * D];
__device__ __half g_y1[NN * D];
__device__ __half g_y2[NN * D];
__device__ float  g_Wt[D * D];
__device__ float  g_Wc[D * D];
__device__ float  g_bt[D];
__device__ float  g_bw[D];

__device__ __forceinline__ uint2 f4_to_h4(float x, float y, float z, float w) {
    __half2 a = __floats2half2_rn(x, y);
    __half2 b = __floats2half2_rn(z, w);
    uint2 u;
    u.x = *(unsigned*)&a;
    u.y = *(unsigned*)&b;
    return u;
}

__device__ __forceinline__ void add_h8(float* a, uint4 v) {
    __half2* h = (__half2*)&v;
    #pragma unroll
    for (int i = 0; i < 4; i++) {
        float2 f = __half22float2(h[i]);
        a[2 * i]     += f.x;
        a[2 * i + 1] += f.y;
    }
}

// ---------------- graph preprocessing (worker stream) ----------------
__global__ void k_hist(const int* __restrict__ src, const int* __restrict__ dst) {
    int i = blockIdx.x * blockDim.x + threadIdx.x;
    if (i < NE / 2) {
        int2 s = __ldg(&((const int2*)src)[i]);
        int2 d = __ldg(&((const int2*)dst)[i]);
        atomicAdd(&g_deg_in[d.x], 1);
        atomicAdd(&g_deg_in[d.y], 1);
        atomicAdd(&g_deg_out[s.x], 1);
        atomicAdd(&g_deg_out[s.y], 1);
    }
}

__global__ void k_partial() {
    __shared__ int ws[8];
    int tid = threadIdx.x, lane = tid & 31, wid = tid >> 5;
    int i = blockIdx.x * 256 + tid;
    int v = (i < NN) ? g_deg_in[i] : 0;
    #pragma unroll
    for (int off = 16; off > 0; off >>= 1) v += __shfl_down_sync(0xffffffffu, v, off);
    if (lane == 0) ws[wid] = v;
    __syncthreads();
    if (tid == 0) {
        int s = 0;
        #pragma unroll
        for (int j = 0; j < 8; j++) s += ws[j];
        g_bsum[blockIdx.x] = s;
    }
}

// fused: block base = sum of g_bsum[0..bid) computed in-kernel; then intra-block scan
__global__ void k_rowptr() {
    __shared__ int ws[8];
    __shared__ int s_base;
    int tid = threadIdx.x, lane = tid & 31, wid = tid >> 5;

    int v0 = (tid < blockIdx.x) ? g_bsum[tid] : 0;
    #pragma unroll
    for (int off = 16; off > 0; off >>= 1) v0 += __shfl_down_sync(0xffffffffu, v0, off);
    if (lane == 0) ws[wid] = v0;
    __syncthreads();
    if (tid == 0) {
        int s = 0;
        #pragma unroll
        for (int j = 0; j < 8; j++) s += ws[j];
        s_base = s;
    }
    __syncthreads();

    int i = blockIdx.x * 256 + tid;
    int v = (i < NN) ? g_deg_in[i] : 0;
    int incl = v;
    #pragma unroll
    for (int off = 1; off < 32; off <<= 1) {
        int t = __shfl_up_sync(0xffffffffu, incl, off);
        if (lane >= off) incl += t;
    }
    if (lane == 31) ws[wid] = incl;
    __syncthreads();
    if (wid == 0 && lane < 8) {
        int s = ws[lane];
        #pragma unroll
        for (int off = 1; off < 8; off <<= 1) {
            int t = __shfl_up_sync(0xffu, s, off);
            if (lane >= off) s += t;
        }
        ws[lane] = s;
    }
    __syncthreads();
    int base = s_base + (wid > 0 ? ws[wid - 1] : 0);
    if (i < NN) {
        int excl = base + incl - v;
        g_row_ptr[i + 1] = base + incl;
        g_cursor[i] = excl;
        int di = v, dq = g_deg_out[i];
        g_invd1[i]   = 1.0f / (float)(di + 1);
        g_innorm[i]  = rsqrtf((float)(di > 0 ? di : 1));
        g_outnorm[i] = rsqrtf((float)(dq > 0 ? dq : 1));
    }
    if (i == 0) g_row_ptr[0] = 0;
}

__global__ void k_scatter(const int* __restrict__ src, const int* __restrict__ dst) {
    int i = blockIdx.x * blockDim.x + threadIdx.x;
    if (i < NE / 2) {
        int2 s = __ldg(&((const int2*)src)[i]);
        int2 d = __ldg(&((const int2*)dst)[i]);
        int p0 = atomicAdd(&g_cursor[d.x], 1);
        g_col[p0] = s.x;
        int p1 = atomicAdd(&g_cursor[d.y], 1);
        g_col[p1] = s.y;
    }
}

// ---------------- fused weight precompute ----------------
__global__ void k_wA(const float* __restrict__ W1, const float* __restrict__ b1,
                     const float* __restrict__ W2, const float* __restrict__ b2) {
    int r = blockIdx.x, c = threadIdx.x;
    __shared__ float arow[D];
    arow[c] = (r < D) ? W1[r * D + c] : b1[c];
    __syncthreads();
    float a0 = 0.f, a1 = 0.f, a2 = 0.f, a3 = 0.f;
    #pragma unroll 8
    for (int k = 0; k < D; k += 4) {
        a0 += arow[k + 0] * __ldg(&W2[(k + 0) * D + c]);
        a1 += arow[k + 1] * __ldg(&W2[(k + 1) * D + c]);
        a2 += arow[k + 2] * __ldg(&W2[(k + 2) * D + c]);
        a3 += arow[k + 3] * __ldg(&W2[(k + 3) * D + c]);
    }
    float acc = (a0 + a1) + (a2 + a3);
    if (r < D) g_Wt[r * D + c] = acc;
    else       g_bt[c] = acc + b2[c];
}
__global__ void k_wB(const float* __restrict__ W3) {
    int r = blockIdx.x, c = threadIdx.x;
    __shared__ float arow[D];
    arow[c] = (r < D) ? g_Wt[r * D + c] : g_bt[c];
    __syncthreads();
    float a0 = 0.f, a1 = 0.f, a2 = 0.f, a3 = 0.f;
    #pragma unroll 8
    for (int k = 0; k < D; k += 4) {
        a0 += arow[k + 0] * __ldg(&W3[(k + 0) * D + c]);
        a1 += arow[k + 1] * __ldg(&W3[(k + 1) * D + c]);
        a2 += arow[k + 2] * __ldg(&W3[(k + 2) * D + c]);
        a3 += arow[k + 3] * __ldg(&W3[(k + 3) * D + c]);
    }
    float acc = (a0 + a1) + (a2 + a3);
    if (r < D) g_Wc[r * D + c] = acc;
    else       g_bw[c] = acc;
}

// ---------------- front GEMM: g_t = x @ Wc  (fp32 in, fp16 out) ----------------
__global__ void k_gemm(const float* __restrict__ x) {
    int t = blockIdx.x * blockDim.x + threadIdx.x;
    int w = t >> 5;
    int lane = t & 31;
    int r0 = w * 4;
    if (r0 >= NN) return;

    const float4* Wc4 = (const float4*)g_Wc;
    const float4* x4  = (const float4*)x;

    float4 acc0 = make_float4(0.f, 0.f, 0.f, 0.f);
    float4 acc1 = acc0, acc2 = acc0, acc3 = acc0;

    #pragma unroll 4
    for (int k = 0; k < D; k += 4) {
        float4 z0 = __ldg(&x4[(size_t)(r0 + 0) * 32 + (k >> 2)]);
        float4 z1 = __ldg(&x4[(size_t)(r0 + 1) * 32 + (k >> 2)]);
        float4 z2 = __ldg(&x4[(size_t)(r0 + 2) * 32 + (k >> 2)]);
        float4 z3 = __ldg(&x4[(size_t)(r0 + 3) * 32 + (k >> 2)]);
        const float* p0 = (const float*)&z0;
        const float* p1 = (const float*)&z1;
        const float* p2 = (const float*)&z2;
        const float* p3 = (const float*)&z3;
        #pragma unroll
        for (int kk = 0; kk < 4; kk++) {
            float4 wv = __ldg(&Wc4[(size_t)(k + kk) * 32 + lane]);
            float a0 = p0[kk], a1 = p1[kk], a2 = p2[kk], a3 = p3[kk];
            acc0.x += a0 * wv.x; acc0.y += a0 * wv.y; acc0.z += a0 * wv.z; acc0.w += a0 * wv.w;
            acc1.x += a1 * wv.x; acc1.y += a1 * wv.y; acc1.z += a1 * wv.z; acc1.w += a1 * wv.w;
            acc2.x += a2 * wv.x; acc2.y += a2 * wv.y; acc2.z += a2 * wv.z; acc2.w += a2 * wv.w;
            acc3.x += a3 * wv.x; acc3.y += a3 * wv.y; acc3.z += a3 * wv.z; acc3.w += a3 * wv.w;
        }
    }

    uint2* t4 = (uint2*)g_t;
    t4[(size_t)(r0 + 0) * 32 + lane] = f4_to_h4(acc0.x, acc0.y, acc0.z, acc0.w);
    t4[(size_t)(r0 + 1) * 32 + lane] = f4_to_h4(acc1.x, acc1.y, acc1.z, acc1.w);
    t4[(size_t)(r0 + 2) * 32 + lane] = f4_to_h4(acc2.x, acc2.y, acc2.z, acc2.w);
    t4[(size_t)(r0 + 3) * 32 + lane] = f4_to_h4(acc3.x, acc3.y, acc3.z, acc3.w);
}

// ---------------- aggregation passes (half-warp per node, pipelined prefetch) ----------
// MODE 0: y1 = (sum_neigh + self) * invd1
// MODE 1: y2 = (sum_neigh + self) * invd1 * outnorm ; g_v[node] = sum outnorm[src]
// MODE 2: out = innorm*sum_neigh + (innorm*g_v[node])*bw + b3  (fp32 out)
template <int MODE>
__global__ __launch_bounds__(256) void k_agg(const __half* __restrict__ hin,
                                             __half* __restrict__ hout,
                                             const float* __restrict__ b3,
                                             float* __restrict__ out) {
    int t = blockIdx.x * 256 + threadIdx.x;
    int w = t >> 5;                       // global warp id
    int lane = threadIdx.x & 31;
    int sl = lane & 15;                   // sub-lane within half-warp
    int node = w * 2 + (lane >> 4);       // 2 nodes per warp
    if (node >= NN) return;

    const uint4* in8 = (const uint4*)hin; // 16B = 8 halves; row = 16 uint4

    float acc[8] = {0.f, 0.f, 0.f, 0.f, 0.f, 0.f, 0.f, 0.f};
    if (MODE < 2) add_h8(acc, __ldg(&in8[(size_t)node * 16 + sl]));
    float vs = 0.f;

    int e   = g_row_ptr[node];
    int end = g_row_ptr[node + 1];

    int cols[8];
    #pragma unroll
    for (int j = 0; j < 8; j++)
        cols[j] = (e + j < end) ? __ldg(&g_col[e + j]) : -1;

    while (e < end) {
        int ne = e + 8;
        int ncols[8];
        #pragma unroll
        for (int j = 0; j < 8; j++)
            ncols[j] = (ne + j < end) ? __ldg(&g_col[ne + j]) : -1;

        #pragma unroll
        for (int j = 0; j < 8; j++) {
            int c = cols[j];
            if (c >= 0) {
                uint4 v = __ldcg(&in8[(size_t)c * 16 + sl]);   // L2-only: no reuse in L1
                add_h8(acc, v);
                if (MODE == 1) vs += __ldg(&g_outnorm[c]);
            }
        }
        #pragma unroll
        for (int j = 0; j < 8; j++) cols[j] = ncols[j];
        e = ne;
    }

    if (MODE < 2) {
        float sc = (MODE == 0) ? g_invd1[node] : g_invd1[node] * g_outnorm[node];
        uint4 u;
        __half2* h = (__half2*)&u;
        #pragma unroll
        for (int i = 0; i < 4; i++)
            h[i] = __floats2half2_rn(acc[2 * i] * sc, acc[2 * i + 1] * sc);
        ((uint4*)hout)[(size_t)node * 16 + sl] = u;
        if (MODE == 1 && sl == 0) g_v[node] = vs;
    } else {
        float sc = g_innorm[node];
        float vb = __ldg(&g_v[node]) * sc;
        const float4* bw4 = (const float4*)g_bw;
        const float4* b34 = (const float4*)b3;
        float4 bwa = __ldg(&bw4[sl * 2]),     b3a = __ldg(&b34[sl * 2]);
        float4 bwb = __ldg(&bw4[sl * 2 + 1]), b3b = __ldg(&b34[sl * 2 + 1]);
        float4 o;
        float4* o4 = (float4*)out;
        o.x = acc[0] * sc + vb * bwa.x + b3a.x;
        o.y = acc[1] * sc + vb * bwa.y + b3a.y;
        o.z = acc[2] * sc + vb * bwa.z + b3a.z;
        o.w = acc[3] * sc + vb * bwa.w + b3a.w;
        o4[(size_t)node * 32 + sl * 2] = o;
        o.x = acc[4] * sc + vb * bwb.x + b3b.x;
        o.y = acc[5] * sc + vb * bwb.y + b3b.y;
        o.z = acc[6] * sc + vb * bwb.z + b3b.z;
        o.w = acc[7] * sc + vb * bwb.w + b3b.w;
        o4[(size_t)node * 32 + sl * 2 + 1] = o;
    }
}

// ---------------- launch ----------------
extern "C" void kernel_launch(void* const* d_in, const int* in_sizes, int n_in,
                              void* d_out, int out_size) {
    const float* x  = (const float*)d_in[0];
    const float* W1 = (const float*)d_in[1];
    const float* b1 = (const float*)d_in[2];
    const float* W2 = (const float*)d_in[3];
    const float* b2 = (const float*)d_in[4];
    const float* W3 = (const float*)d_in[5];
    const float* b3 = (const float*)d_in[6];
    const int* src  = (const int*)d_in[7];
    const int* dst  = (const int*)d_in[8];
    float* out = (float*)d_out;

    __half *tptr, *y1, *y2;
    void *din, *dout_deg;
    cudaGetSymbolAddress((void**)&tptr, g_t);
    cudaGetSymbolAddress((void**)&y1, g_y1);
    cudaGetSymbolAddress((void**)&y2, g_y2);
    cudaGetSymbolAddress(&din, g_deg_in);
    cudaGetSymbolAddress(&dout_deg, g_deg_out);

    static cudaStream_t s1 = 0;
    static cudaEvent_t evA = 0, evB = 0;
    if (!s1) {
        cudaStreamCreateWithFlags(&s1, cudaStreamNonBlocking);
        cudaEventCreateWithFlags(&evA, cudaEventDisableTiming);
        cudaEventCreateWithFlags(&evB, cudaEventDisableTiming);
    }

    // ---- fork: CSR build on worker stream s1 ----
    cudaEventRecord(evA, 0);
    cudaStreamWaitEvent(s1, evA, 0);
    cudaMemsetAsync(din, 0, NN * sizeof(int), s1);
    cudaMemsetAsync(dout_deg, 0, NN * sizeof(int), s1);
    k_hist   <<<(NE / 2 + 255) / 256, 256, 0, s1>>>(src, dst);
    k_partial<<<NB, 256, 0, s1>>>();
    k_rowptr <<<NB, 256, 0, s1>>>();
    k_scatter<<<(NE / 2 + 255) / 256, 256, 0, s1>>>(src, dst);
    cudaEventRecord(evB, s1);

    // ---- main stream: weights -> front GEMM ----
    k_wA<<<D + 1, D>>>(W1, b1, W2, b2);
    k_wB<<<D + 1, D>>>(W3);

    const int FIN_WARPS = (NN + 3) / 4;
    const int FIN_BLOCKS = (FIN_WARPS * 32 + 255) / 256;
    k_gemm<<<FIN_BLOCKS, 256>>>(x);

    // ---- join: agg passes need both GEMM output and CSR ----
    cudaStreamWaitEvent(0, evB, 0);

    const int AGG_WARPS = (NN + 1) / 2;                    // 25000
    const int AGG_BLOCKS = (AGG_WARPS * 32 + 255) / 256;   // 3125
    k_agg<0><<<AGG_BLOCKS, 256>>>(tptr, y1, nullptr, nullptr);
    k_agg<1><<<AGG_BLOCKS, 256>>>(y1, y2, nullptr, nullptr);
    k_agg<2><<<AGG_BLOCKS, 256>>>(y2, nullptr, b3, out);
}